// round 2
// baseline (speedup 1.0000x reference)
#include <cuda_runtime.h>
#include <math.h>

#define E_  512
#define H_  8
#define HD_ 64
#define F_  32
#define L_  3
#define V_  32000
#define B_  128
#define T_  16
#define SOS_ 1

// ---------------- scratch (static device globals; no allocation) ----------------
__device__ float g_tb[T_*B_*E_];        // tok_before embeddings (grows by 1 row/step)
__device__ float g_x[T_*B_*E_];         // working activations
__device__ float g_qkv[T_*B_*3*E_];
__device__ float g_attn[T_*B_*E_];
__device__ float g_tmp[T_*B_*E_];
__device__ float g_h[T_*B_*F_];
__device__ float g_c[L_*B_*E_];         // precomputed cross-attn constants
__device__ float g_hv[B_*E_];
__device__ float g_pe[T_*E_];
__device__ float g_logits[B_*V_];
__device__ int   g_tok[B_];

// ---------------- generic SGEMM: C[M,N] = A[M,K] @ W[N,K]^T + bias ----------------
// 128x128 tile, BK=8, 256 threads, 8x8 micro-tile per thread.
// Requires: M % 128 == 0, K % 8 == 0. N guarded (handles N=32).
__global__ __launch_bounds__(256) void gemm_nt(
    const float* __restrict__ A, const float* __restrict__ W,
    const float* __restrict__ bias, float* __restrict__ C,
    int M, int N, int K, int relu)
{
    __shared__ float As[8][128];
    __shared__ float Ws[8][128];
    const int m0 = blockIdx.y * 128;
    const int n0 = blockIdx.x * 128;
    const int tid = threadIdx.x;
    const int tm = tid >> 4;          // 0..15, covers 8 M rows
    const int tn = tid & 15;          // 0..15, covers 8 N cols

    float acc[8][8];
#pragma unroll
    for (int i = 0; i < 8; i++)
#pragma unroll
        for (int j = 0; j < 8; j++) acc[i][j] = 0.f;

    const int lrow = tid >> 1;        // 0..127
    const int lkk  = (tid & 1) * 4;   // 0 or 4

    for (int k0 = 0; k0 < K; k0 += 8) {
        float4 av = *reinterpret_cast<const float4*>(&A[(size_t)(m0 + lrow) * K + k0 + lkk]);
        float4 wv;
        if (n0 + lrow < N)
            wv = *reinterpret_cast<const float4*>(&W[(size_t)(n0 + lrow) * K + k0 + lkk]);
        else
            wv = make_float4(0.f, 0.f, 0.f, 0.f);
        As[lkk + 0][lrow] = av.x; As[lkk + 1][lrow] = av.y;
        As[lkk + 2][lrow] = av.z; As[lkk + 3][lrow] = av.w;
        Ws[lkk + 0][lrow] = wv.x; Ws[lkk + 1][lrow] = wv.y;
        Ws[lkk + 2][lrow] = wv.z; Ws[lkk + 3][lrow] = wv.w;
        __syncthreads();
#pragma unroll
        for (int kk = 0; kk < 8; kk++) {
            float a[8], w[8];
#pragma unroll
            for (int i = 0; i < 8; i++) a[i] = As[kk][tm * 8 + i];
#pragma unroll
            for (int j = 0; j < 8; j++) w[j] = Ws[kk][tn * 8 + j];
#pragma unroll
            for (int i = 0; i < 8; i++)
#pragma unroll
                for (int j = 0; j < 8; j++)
                    acc[i][j] = fmaf(a[i], w[j], acc[i][j]);
        }
        __syncthreads();
    }

#pragma unroll
    for (int i = 0; i < 8; i++) {
        int m = m0 + tm * 8 + i;
#pragma unroll
        for (int j = 0; j < 8; j++) {
            int n = n0 + tn * 8 + j;
            if (n < N) {
                float cv = acc[i][j] + bias[n];
                if (relu) cv = fmaxf(cv, 0.f);
                C[(size_t)m * N + n] = cv;
            }
        }
    }
}

// ---------------- self-attention (tiny: S<=16, per (b,h) block) ----------------
__global__ __launch_bounds__(256) void self_attn(
    const float* __restrict__ qkv, float* __restrict__ out, int S)
{
    const int b = blockIdx.x, h = blockIdx.y;
    __shared__ float q[T_][HD_ + 1], k[T_][HD_ + 1], v[T_][HD_ + 1];
    __shared__ float p[T_][T_ + 1];
    const int tid = threadIdx.x;

    for (int idx = tid; idx < S * HD_; idx += 256) {
        int s = idx >> 6, d = idx & 63;
        size_t base = ((size_t)(s * B_ + b)) * (3 * E_) + h * HD_ + d;
        q[s][d] = qkv[base];
        k[s][d] = qkv[base + E_];
        v[s][d] = qkv[base + 2 * E_];
    }
    __syncthreads();

    for (int idx = tid; idx < S * S; idx += 256) {
        int sq = idx / S, sk = idx - sq * S;
        float acc = 0.f;
#pragma unroll
        for (int d = 0; d < HD_; d++) acc = fmaf(q[sq][d], k[sk][d], acc);
        p[sq][sk] = acc * 0.125f;   // 1/sqrt(64)
    }
    __syncthreads();

    if (tid < S) {
        float mx = -3.4e38f;
        for (int sk = 0; sk < S; sk++) mx = fmaxf(mx, p[tid][sk]);
        float sum = 0.f;
        for (int sk = 0; sk < S; sk++) { float e = expf(p[tid][sk] - mx); p[tid][sk] = e; sum += e; }
        float inv = 1.f / sum;
        for (int sk = 0; sk < S; sk++) p[tid][sk] *= inv;
    }
    __syncthreads();

    for (int idx = tid; idx < S * HD_; idx += 256) {
        int s = idx >> 6, d = idx & 63;
        float acc = 0.f;
        for (int sk = 0; sk < S; sk++) acc = fmaf(p[s][sk], v[sk][d], acc);
        out[((size_t)(s * B_ + b)) * E_ + h * HD_ + d] = acc;
    }
}

// ---------------- fused residual-add + LayerNorm (in place on x) ----------------
__global__ __launch_bounds__(256) void ln_add(
    float* __restrict__ x, const float* __restrict__ add,
    const float* __restrict__ g, const float* __restrict__ beta, int bcast)
{
    const int row  = blockIdx.x;
    const int arow = bcast ? (row & (B_ - 1)) : row;
    const int tid  = threadIdx.x;
    float* xr = x + (size_t)row * E_;
    const float* ar = add + (size_t)arow * E_;

    float v0 = xr[tid] + ar[tid];
    float v1 = xr[tid + 256] + ar[tid + 256];

    __shared__ float red1[8], red2[8];

    float s = v0 + v1;
    for (int o = 16; o; o >>= 1) s += __shfl_down_sync(0xffffffffu, s, o);
    if ((tid & 31) == 0) red1[tid >> 5] = s;
    __syncthreads();
    if (tid < 8) {
        s = red1[tid];
        for (int o = 4; o; o >>= 1) s += __shfl_down_sync(0xffu, s, o);
        if (tid == 0) red1[0] = s;
    }
    __syncthreads();
    float mean = red1[0] * (1.0f / (float)E_);

    float d0 = v0 - mean, d1 = v1 - mean;
    float q = d0 * d0 + d1 * d1;
    for (int o = 16; o; o >>= 1) q += __shfl_down_sync(0xffffffffu, q, o);
    if ((tid & 31) == 0) red2[tid >> 5] = q;
    __syncthreads();
    if (tid < 8) {
        q = red2[tid];
        for (int o = 4; o; o >>= 1) q += __shfl_down_sync(0xffu, q, o);
        if (tid == 0) red2[0] = q;
    }
    __syncthreads();
    float var = red2[0] * (1.0f / (float)E_);
    float rstd = 1.0f / sqrtf(var + 1e-5f);

    xr[tid]       = d0 * rstd * g[tid]       + beta[tid];
    xr[tid + 256] = d1 * rstd * g[tid + 256] + beta[tid + 256];
}

// ---------------- softmax + argmax + prob write + token record ----------------
__global__ __launch_bounds__(256) void softmax_tok(
    const float* __restrict__ logits, float* __restrict__ probs,
    float* __restrict__ tokf, int* __restrict__ tok, int step)
{
    const int b = blockIdx.x;
    const float* row = logits + (size_t)b * V_;
    const int tid = threadIdx.x;
    __shared__ float smx[256];
    __shared__ int   sidx[256];

    float mx = -3.4e38f; int mi = 0;
    for (int v = tid; v < V_; v += 256) {
        float val = row[v];
        if (val > mx) { mx = val; mi = v; }
    }
    smx[tid] = mx; sidx[tid] = mi;
    __syncthreads();
    for (int o = 128; o; o >>= 1) {
        if (tid < o) {
            float om = smx[tid + o]; int oi = sidx[tid + o];
            if (om > smx[tid] || (om == smx[tid] && oi < sidx[tid])) {
                smx[tid] = om; sidx[tid] = oi;
            }
        }
        __syncthreads();
    }
    float m = smx[0];
    int amax = sidx[0];
    __syncthreads();

    float sum = 0.f;
    for (int v = tid; v < V_; v += 256) sum += expf(row[v] - m);
    smx[tid] = sum;
    __syncthreads();
    for (int o = 128; o; o >>= 1) {
        if (tid < o) smx[tid] += smx[tid + o];
        __syncthreads();
    }
    float inv = 1.0f / smx[0];

    for (int v = tid; v < V_; v += 256)
        probs[(size_t)b * V_ + v] = expf(row[v] - m) * inv;

    if (tid == 0) {
        tok[b] = amax;
        if (tokf) tokf[(size_t)b * T_ + step] = (float)amax;
    }
}

// ---------------- misc small kernels ----------------
__global__ void pe_init(float* __restrict__ pe)
{
    int t = blockIdx.x;
    for (int i = threadIdx.x; i < E_ / 2; i += 256) {
        float div = expf((float)(2 * i) * (-logf(10000.0f) / (float)E_));
        float arg = (float)t * div;
        pe[t * E_ + 2 * i]     = sinf(arg);
        pe[t * E_ + 2 * i + 1] = cosf(arg);
    }
}

__global__ void init_x(const float* __restrict__ emb, float* __restrict__ tb)
{
    int b = blockIdx.x;
    for (int e = threadIdx.x; e < E_; e += 256)
        tb[(size_t)b * E_ + e] = emb[(size_t)SOS_ * E_ + e];
}

__global__ void append_tok(const float* __restrict__ emb, float* __restrict__ tb,
                           const float* __restrict__ pe, const int* __restrict__ tok, int step)
{
    int b = blockIdx.x;
    int t = tok[b];
    size_t dst = ((size_t)(step + 1) * B_ + b) * E_;
    for (int e = threadIdx.x; e < E_; e += 256)
        tb[dst + e] = emb[(size_t)t * E_ + e] + pe[step * E_ + e];
}

__global__ void copy4(float4* __restrict__ dst, const float4* __restrict__ src)
{
    int i = blockIdx.x * 256 + threadIdx.x;
    dst[i] = src[i];
}

// ---------------- launcher ----------------
extern "C" void kernel_launch(void* const* d_in, const int* in_sizes, int n_in,
                              void* d_out, int out_size)
{
    const float* cur      = (const float*)d_in[0];
    const float* emb      = (const float*)d_in[1];
    const float* sa_in_w  = (const float*)d_in[2];
    const float* sa_in_b  = (const float*)d_in[3];
    const float* sa_out_w = (const float*)d_in[4];
    const float* sa_out_b = (const float*)d_in[5];
    const float* ca_in_w  = (const float*)d_in[6];
    const float* ca_in_b  = (const float*)d_in[7];
    const float* ca_out_w = (const float*)d_in[8];
    const float* ca_out_b = (const float*)d_in[9];
    const float* ff1_w    = (const float*)d_in[10];
    const float* ff1_b    = (const float*)d_in[11];
    const float* ff2_w    = (const float*)d_in[12];
    const float* ff2_b    = (const float*)d_in[13];
    const float* ln_g     = (const float*)d_in[14];
    const float* ln_b     = (const float*)d_in[15];
    const float* out_w    = (const float*)d_in[16];
    const float* out_b    = (const float*)d_in[17];
    // d_in[18] = max_length (fixed T_=16 for this problem)

    float *tb, *x, *qkv, *attn, *tmp, *hb, *cb, *hv, *pe, *logits;
    int* tok;
    cudaGetSymbolAddress((void**)&tb,     g_tb);
    cudaGetSymbolAddress((void**)&x,      g_x);
    cudaGetSymbolAddress((void**)&qkv,    g_qkv);
    cudaGetSymbolAddress((void**)&attn,   g_attn);
    cudaGetSymbolAddress((void**)&tmp,    g_tmp);
    cudaGetSymbolAddress((void**)&hb,     g_h);
    cudaGetSymbolAddress((void**)&cb,     g_c);
    cudaGetSymbolAddress((void**)&hv,     g_hv);
    cudaGetSymbolAddress((void**)&pe,     g_pe);
    cudaGetSymbolAddress((void**)&logits, g_logits);
    cudaGetSymbolAddress((void**)&tok,    g_tok);

    float* outp = (float*)d_out;
    long long tok_elems = (long long)out_size - (long long)T_ * B_ * V_;
    float* tokf = (tok_elems > 0) ? outp : nullptr;
    float* probs_base = (tok_elems > 0) ? (outp + tok_elems) : outp;

    pe_init<<<T_, 256>>>(pe);
    init_x<<<B_, 256>>>(emb, tb);

    // Cross-attention collapses (kv seq len == 1 => softmax == 1):
    // c[l][b] = ca_out_w[l] @ (ca_wv[l] @ hx_b + bv) + ca_out_b[l]  — precompute once.
    for (int l = 0; l < L_; l++) {
        gemm_nt<<<dim3(E_ / 128, B_ / 128), 256>>>(
            cur, ca_in_w + ((size_t)l * 3 * E_ + 2 * E_) * E_,
            ca_in_b + (size_t)l * 3 * E_ + 2 * E_, hv, B_, E_, E_, 0);
        gemm_nt<<<dim3(E_ / 128, B_ / 128), 256>>>(
            hv, ca_out_w + (size_t)l * E_ * E_, ca_out_b + (size_t)l * E_,
            cb + (size_t)l * B_ * E_, B_, E_, E_, 0);
    }

    for (int i = 0; i < T_; i++) {
        const int S = i + 1;
        const int M = S * B_;

        // x = copy(tok_before[0:S])
        copy4<<<S * (B_ * E_ / 4 / 256), 256>>>((float4*)x, (const float4*)tb);

        for (int l = 0; l < L_; l++) {
            // self-attention
            gemm_nt<<<dim3(3 * E_ / 128, M / 128), 256>>>(
                x, sa_in_w + (size_t)l * 3 * E_ * E_, sa_in_b + (size_t)l * 3 * E_,
                qkv, M, 3 * E_, E_, 0);
            self_attn<<<dim3(B_, H_), 256>>>(qkv, attn, S);
            gemm_nt<<<dim3(E_ / 128, M / 128), 256>>>(
                attn, sa_out_w + (size_t)l * E_ * E_, sa_out_b + (size_t)l * E_,
                tmp, M, E_, E_, 0);
            ln_add<<<M, 256>>>(x, tmp, ln_g + (size_t)(l * 3 + 0) * E_,
                               ln_b + (size_t)(l * 3 + 0) * E_, 0);
            // cross-attention (precomputed constant, broadcast over seq)
            ln_add<<<M, 256>>>(x, cb + (size_t)l * B_ * E_,
                               ln_g + (size_t)(l * 3 + 1) * E_,
                               ln_b + (size_t)(l * 3 + 1) * E_, 1);
            // feed-forward
            gemm_nt<<<dim3(1, M / 128), 256>>>(
                x, ff1_w + (size_t)l * F_ * E_, ff1_b + (size_t)l * F_,
                hb, M, F_, E_, 1);
            gemm_nt<<<dim3(E_ / 128, M / 128), 256>>>(
                hb, ff2_w + (size_t)l * E_ * F_, ff2_b + (size_t)l * E_,
                tmp, M, E_, F_, 0);
            ln_add<<<M, 256>>>(x, tmp, ln_g + (size_t)(l * 3 + 2) * E_,
                               ln_b + (size_t)(l * 3 + 2) * E_, 0);
        }

        // logits for last position, then softmax/argmax/probs
        gemm_nt<<<dim3(V_ / 128, B_ / 128), 256>>>(
            x + (size_t)(S - 1) * B_ * E_, out_w, out_b, logits, B_, V_, E_, 0);
        softmax_tok<<<B_, 256>>>(logits, probs_base + (size_t)i * B_ * V_, tokf, tok, i);

        if (i + 1 < T_)
            append_tok<<<B_, 256>>>(emb, tb, pe, tok, i);
    }
}

// round 3
// speedup vs baseline: 2.0050x; 2.0050x over previous
#include <cuda_runtime.h>
#include <math.h>

#define E_  512
#define H_  8
#define HD_ 64
#define F_  32
#define L_  3
#define V_  32000
#define B_  128
#define T_  16
#define SOS_ 1

// ---------------- scratch (static device globals; no allocation) ----------------
__device__ float g_tb[T_*B_*E_];          // tok_before embeddings
__device__ float g_x[T_*B_*E_];           // working activations
__device__ float g_qkv0[T_*B_*3*E_];      // layer-0 QKV cache (rows immutable)
__device__ float g_qkv[T_*B_*3*E_];       // layers 1-2 QKV
__device__ float g_attn[T_*B_*E_];
__device__ float g_tmp[T_*B_*E_];
__device__ float g_c[L_*B_*E_];           // precomputed cross-attn constants
__device__ float g_hv[B_*E_];
__device__ float g_pe[T_*E_];
__device__ float g_logits[B_*V_];
__device__ int   g_tok[B_];

// ---------------- packed fp32x2 helpers ----------------
__device__ __forceinline__ unsigned long long dupf(float f) {
    unsigned long long r; unsigned u = __float_as_uint(f);
    asm("mov.b64 %0, {%1, %1};" : "=l"(r) : "r"(u));
    return r;
}
__device__ __forceinline__ void ffma2(unsigned long long& d,
                                      unsigned long long a,
                                      unsigned long long b) {
    asm("fma.rn.f32x2 %0, %1, %2, %0;" : "+l"(d) : "l"(a), "l"(b));
}

// ================= GEMM 128x128 tile, f32x2, double-buffered =================
// C[M,N] = A[M,K] @ W[N,K]^T + bias. Requires M%128==0, N%128==0, K%8==0.
__global__ __launch_bounds__(256, 2) void gemm128(
    const float* __restrict__ A, const float* __restrict__ W,
    const float* __restrict__ bias, float* __restrict__ C,
    int M, int N, int K, int relu)
{
    __shared__ float As[2][8][128];
    __shared__ unsigned long long Wd[2][8][128];  // (w,w) duplicated pairs

    const int m0 = blockIdx.y * 128;
    const int n0 = blockIdx.x * 128;
    const int tid = threadIdx.x;
    const int tm = tid >> 4;          // 0..15 -> 8 M rows (as 4 pairs)
    const int tn = tid & 15;          // 0..15 -> 8 N cols (stride 16)
    const int lrow = tid >> 1;        // 0..127
    const int lk   = (tid & 1) * 4;   // 0 or 4

    const float* Aptr = A + (size_t)(m0 + lrow) * K + lk;
    const float* Wptr = W + (size_t)(n0 + lrow) * K + lk;

    unsigned long long acc[4][8];
#pragma unroll
    for (int q = 0; q < 4; q++)
#pragma unroll
        for (int j = 0; j < 8; j++) acc[q][j] = 0ull;

    float4 av = *reinterpret_cast<const float4*>(Aptr);
    float4 wv = *reinterpret_cast<const float4*>(Wptr);
    As[0][lk+0][lrow] = av.x; As[0][lk+1][lrow] = av.y;
    As[0][lk+2][lrow] = av.z; As[0][lk+3][lrow] = av.w;
    Wd[0][lk+0][lrow] = dupf(wv.x); Wd[0][lk+1][lrow] = dupf(wv.y);
    Wd[0][lk+2][lrow] = dupf(wv.z); Wd[0][lk+3][lrow] = dupf(wv.w);
    __syncthreads();

    const int NT = K >> 3;
    int buf = 0;
    for (int t = 0; t < NT; t++) {
        if (t + 1 < NT) {
            av = *reinterpret_cast<const float4*>(Aptr + (t + 1) * 8);
            wv = *reinterpret_cast<const float4*>(Wptr + (t + 1) * 8);
        }
#pragma unroll
        for (int kk = 0; kk < 8; kk++) {
            unsigned long long a2[4], w2[8];
#pragma unroll
            for (int q = 0; q < 4; q++)
                a2[q] = *reinterpret_cast<const unsigned long long*>(
                            &As[buf][kk][tm * 8 + 2 * q]);
#pragma unroll
            for (int j = 0; j < 8; j++)
                w2[j] = Wd[buf][kk][tn + 16 * j];
#pragma unroll
            for (int q = 0; q < 4; q++)
#pragma unroll
                for (int j = 0; j < 8; j++)
                    ffma2(acc[q][j], a2[q], w2[j]);
        }
        if (t + 1 < NT) {
            buf ^= 1;
            As[buf][lk+0][lrow] = av.x; As[buf][lk+1][lrow] = av.y;
            As[buf][lk+2][lrow] = av.z; As[buf][lk+3][lrow] = av.w;
            Wd[buf][lk+0][lrow] = dupf(wv.x); Wd[buf][lk+1][lrow] = dupf(wv.y);
            Wd[buf][lk+2][lrow] = dupf(wv.z); Wd[buf][lk+3][lrow] = dupf(wv.w);
            __syncthreads();
        }
    }

#pragma unroll
    for (int q = 0; q < 4; q++) {
        int m = m0 + tm * 8 + 2 * q;
#pragma unroll
        for (int j = 0; j < 8; j++) {
            int n = n0 + tn + 16 * j;
            float2 v = *reinterpret_cast<float2*>(&acc[q][j]);
            float c0 = v.x + bias[n];
            float c1 = v.y + bias[n];
            if (relu) { c0 = fmaxf(c0, 0.f); c1 = fmaxf(c1, 0.f); }
            C[(size_t)m * N + n]       = c0;
            C[(size_t)(m + 1) * N + n] = c1;
        }
    }
}

// ================= GEMM 64x64 tile, f32x2 (for small grids) =================
// Requires M%64==0, N%64==0, K%16==0.
__global__ __launch_bounds__(128, 4) void gemm64(
    const float* __restrict__ A, const float* __restrict__ W,
    const float* __restrict__ bias, float* __restrict__ C,
    int M, int N, int K, int relu)
{
    __shared__ float As[2][16][64];
    __shared__ unsigned long long Wd[2][16][64];

    const int m0 = blockIdx.y * 64;
    const int n0 = blockIdx.x * 64;
    const int tid = threadIdx.x;
    const int tm = tid >> 3;          // 0..15 -> 4 M rows (2 pairs)
    const int tn = tid & 7;           // 0..7 -> 8 N cols (stride 8)
    const int lrow = tid >> 1;        // 0..63
    const int lk   = (tid & 1) * 8;   // 0 or 8

    const float* Aptr = A + (size_t)(m0 + lrow) * K + lk;
    const float* Wptr = W + (size_t)(n0 + lrow) * K + lk;

    unsigned long long acc[2][8];
#pragma unroll
    for (int q = 0; q < 2; q++)
#pragma unroll
        for (int j = 0; j < 8; j++) acc[q][j] = 0ull;

    float4 av0 = *reinterpret_cast<const float4*>(Aptr);
    float4 av1 = *reinterpret_cast<const float4*>(Aptr + 4);
    float4 wv0 = *reinterpret_cast<const float4*>(Wptr);
    float4 wv1 = *reinterpret_cast<const float4*>(Wptr + 4);
    As[0][lk+0][lrow]=av0.x; As[0][lk+1][lrow]=av0.y; As[0][lk+2][lrow]=av0.z; As[0][lk+3][lrow]=av0.w;
    As[0][lk+4][lrow]=av1.x; As[0][lk+5][lrow]=av1.y; As[0][lk+6][lrow]=av1.z; As[0][lk+7][lrow]=av1.w;
    Wd[0][lk+0][lrow]=dupf(wv0.x); Wd[0][lk+1][lrow]=dupf(wv0.y); Wd[0][lk+2][lrow]=dupf(wv0.z); Wd[0][lk+3][lrow]=dupf(wv0.w);
    Wd[0][lk+4][lrow]=dupf(wv1.x); Wd[0][lk+5][lrow]=dupf(wv1.y); Wd[0][lk+6][lrow]=dupf(wv1.z); Wd[0][lk+7][lrow]=dupf(wv1.w);
    __syncthreads();

    const int NT = K >> 4;
    int buf = 0;
    for (int t = 0; t < NT; t++) {
        if (t + 1 < NT) {
            av0 = *reinterpret_cast<const float4*>(Aptr + (t + 1) * 16);
            av1 = *reinterpret_cast<const float4*>(Aptr + (t + 1) * 16 + 4);
            wv0 = *reinterpret_cast<const float4*>(Wptr + (t + 1) * 16);
            wv1 = *reinterpret_cast<const float4*>(Wptr + (t + 1) * 16 + 4);
        }
#pragma unroll
        for (int kk = 0; kk < 16; kk++) {
            unsigned long long a2[2], w2[8];
#pragma unroll
            for (int q = 0; q < 2; q++)
                a2[q] = *reinterpret_cast<const unsigned long long*>(
                            &As[buf][kk][tm * 4 + 2 * q]);
#pragma unroll
            for (int j = 0; j < 8; j++)
                w2[j] = Wd[buf][kk][tn + 8 * j];
#pragma unroll
            for (int q = 0; q < 2; q++)
#pragma unroll
                for (int j = 0; j < 8; j++)
                    ffma2(acc[q][j], a2[q], w2[j]);
        }
        if (t + 1 < NT) {
            buf ^= 1;
            As[buf][lk+0][lrow]=av0.x; As[buf][lk+1][lrow]=av0.y; As[buf][lk+2][lrow]=av0.z; As[buf][lk+3][lrow]=av0.w;
            As[buf][lk+4][lrow]=av1.x; As[buf][lk+5][lrow]=av1.y; As[buf][lk+6][lrow]=av1.z; As[buf][lk+7][lrow]=av1.w;
            Wd[buf][lk+0][lrow]=dupf(wv0.x); Wd[buf][lk+1][lrow]=dupf(wv0.y); Wd[buf][lk+2][lrow]=dupf(wv0.z); Wd[buf][lk+3][lrow]=dupf(wv0.w);
            Wd[buf][lk+4][lrow]=dupf(wv1.x); Wd[buf][lk+5][lrow]=dupf(wv1.y); Wd[buf][lk+6][lrow]=dupf(wv1.z); Wd[buf][lk+7][lrow]=dupf(wv1.w);
            __syncthreads();
        }
    }

#pragma unroll
    for (int q = 0; q < 2; q++) {
        int m = m0 + tm * 4 + 2 * q;
#pragma unroll
        for (int j = 0; j < 8; j++) {
            int n = n0 + tn + 8 * j;
            float2 v = *reinterpret_cast<float2*>(&acc[q][j]);
            float c0 = v.x + bias[n];
            float c1 = v.y + bias[n];
            if (relu) { c0 = fmaxf(c0, 0.f); c1 = fmaxf(c1, 0.f); }
            C[(size_t)m * N + n]       = c0;
            C[(size_t)(m + 1) * N + n] = c1;
        }
    }
}

// ---------------- block reduction helper (256 threads) ----------------
__device__ __forceinline__ float blocksum256(float v)
{
    __shared__ float red[8];
    for (int o = 16; o; o >>= 1) v += __shfl_down_sync(0xffffffffu, v, o);
    if ((threadIdx.x & 31) == 0) red[threadIdx.x >> 5] = v;
    __syncthreads();
    if (threadIdx.x < 32) {
        float s = (threadIdx.x < 8) ? red[threadIdx.x] : 0.f;
        for (int o = 4; o; o >>= 1) s += __shfl_down_sync(0xffffffffu, s, o);
        if (threadIdx.x == 0) red[0] = s;
    }
    __syncthreads();
    float r = red[0];
    __syncthreads();
    return r;
}

// ---------------- self-attention (S<=16, per (b,h) block) ----------------
__global__ __launch_bounds__(256) void self_attn(
    const float* __restrict__ qkv, float* __restrict__ out, int S)
{
    const int b = blockIdx.x, h = blockIdx.y;
    __shared__ float q[T_][HD_ + 1], k[T_][HD_ + 1], v[T_][HD_ + 1];
    __shared__ float p[T_][T_ + 1];
    const int tid = threadIdx.x;

    for (int idx = tid; idx < S * HD_; idx += 256) {
        int s = idx >> 6, d = idx & 63;
        size_t base = ((size_t)(s * B_ + b)) * (3 * E_) + h * HD_ + d;
        q[s][d] = qkv[base];
        k[s][d] = qkv[base + E_];
        v[s][d] = qkv[base + 2 * E_];
    }
    __syncthreads();

    for (int idx = tid; idx < S * S; idx += 256) {
        int sq = idx / S, sk = idx - sq * S;
        float acc = 0.f;
#pragma unroll
        for (int d = 0; d < HD_; d++) acc = fmaf(q[sq][d], k[sk][d], acc);
        p[sq][sk] = acc * 0.125f;
    }
    __syncthreads();

    if (tid < S) {
        float mx = -3.4e38f;
        for (int sk = 0; sk < S; sk++) mx = fmaxf(mx, p[tid][sk]);
        float sum = 0.f;
        for (int sk = 0; sk < S; sk++) { float e = expf(p[tid][sk] - mx); p[tid][sk] = e; sum += e; }
        float inv = 1.f / sum;
        for (int sk = 0; sk < S; sk++) p[tid][sk] *= inv;
    }
    __syncthreads();

    for (int idx = tid; idx < S * HD_; idx += 256) {
        int s = idx >> 6, d = idx & 63;
        float acc = 0.f;
        for (int sk = 0; sk < S; sk++) acc = fmaf(p[s][sk], v[sk][d], acc);
        out[((size_t)(s * B_ + b)) * E_ + h * HD_ + d] = acc;
    }
}

// -------- fused: x = LN(x+add, g0,b0); x = LN(x + c[b], g1,b1) --------
__global__ __launch_bounds__(256) void ln2_add(
    float* __restrict__ x, const float* __restrict__ add,
    const float* __restrict__ c,
    const float* __restrict__ g0, const float* __restrict__ b0,
    const float* __restrict__ g1, const float* __restrict__ b1)
{
    const int row = blockIdx.x;
    const int bb  = row & (B_ - 1);
    const int tid = threadIdx.x;
    float* xr = x + (size_t)row * E_;
    const float* ar = add + (size_t)row * E_;
    const float* cr = c + (size_t)bb * E_;

    float v0 = xr[tid] + ar[tid];
    float v1 = xr[tid + 256] + ar[tid + 256];

    float mean = blocksum256(v0 + v1) * (1.0f / (float)E_);
    float d0 = v0 - mean, d1 = v1 - mean;
    float var = blocksum256(d0 * d0 + d1 * d1) * (1.0f / (float)E_);
    float rs = rsqrtf(var + 1e-5f);
    float y0 = d0 * rs * g0[tid]       + b0[tid]       + cr[tid];
    float y1 = d1 * rs * g0[tid + 256] + b0[tid + 256] + cr[tid + 256];

    float mean2 = blocksum256(y0 + y1) * (1.0f / (float)E_);
    float e0 = y0 - mean2, e1 = y1 - mean2;
    float var2 = blocksum256(e0 * e0 + e1 * e1) * (1.0f / (float)E_);
    float rs2 = rsqrtf(var2 + 1e-5f);
    xr[tid]       = e0 * rs2 * g1[tid]       + b1[tid];
    xr[tid + 256] = e1 * rs2 * g1[tid + 256] + b1[tid + 256];
}

// -------- fused FF: x = LN(x + ff2(relu(ff1(x)))), one row per block --------
__global__ __launch_bounds__(256) void ff_fused(
    float* __restrict__ x,
    const float* __restrict__ w1, const float* __restrict__ b1,
    const float* __restrict__ w2, const float* __restrict__ b2,
    const float* __restrict__ g, const float* __restrict__ beta)
{
    const int row = blockIdx.x;
    const int tid = threadIdx.x;
    __shared__ float xs[E_];
    __shared__ float hs[F_];
    float* xr = x + (size_t)row * E_;

    xs[tid] = xr[tid];
    xs[tid + 256] = xr[tid + 256];
    __syncthreads();

    const int u = tid >> 3, l = tid & 7;
    const float4* w4  = reinterpret_cast<const float4*>(w1 + (size_t)u * E_);
    const float4* xs4 = reinterpret_cast<const float4*>(xs);
    float p = 0.f;
#pragma unroll
    for (int k4 = 0; k4 < 16; k4++) {
        float4 wv = w4[l + 8 * k4];
        float4 xv = xs4[l + 8 * k4];
        p += wv.x * xv.x + wv.y * xv.y + wv.z * xv.z + wv.w * xv.w;
    }
    for (int o = 4; o; o >>= 1) p += __shfl_down_sync(0xffffffffu, p, o, 8);
    if (l == 0) hs[u] = fmaxf(p + b1[u], 0.f);
    __syncthreads();

    float a0 = b2[tid]       + xs[tid];
    float a1 = b2[tid + 256] + xs[tid + 256];
    const float4* w20 = reinterpret_cast<const float4*>(w2 + (size_t)tid * F_);
    const float4* w21 = reinterpret_cast<const float4*>(w2 + (size_t)(tid + 256) * F_);
#pragma unroll
    for (int c4 = 0; c4 < 8; c4++) {
        float4 wa = w20[c4], wb = w21[c4];
        a0 = fmaf(hs[4*c4+0], wa.x, a0); a0 = fmaf(hs[4*c4+1], wa.y, a0);
        a0 = fmaf(hs[4*c4+2], wa.z, a0); a0 = fmaf(hs[4*c4+3], wa.w, a0);
        a1 = fmaf(hs[4*c4+0], wb.x, a1); a1 = fmaf(hs[4*c4+1], wb.y, a1);
        a1 = fmaf(hs[4*c4+2], wb.z, a1); a1 = fmaf(hs[4*c4+3], wb.w, a1);
    }

    float mean = blocksum256(a0 + a1) * (1.0f / (float)E_);
    float d0 = a0 - mean, d1 = a1 - mean;
    float var = blocksum256(d0 * d0 + d1 * d1) * (1.0f / (float)E_);
    float rs = rsqrtf(var + 1e-5f);
    xr[tid]       = d0 * rs * g[tid]       + beta[tid];
    xr[tid + 256] = d1 * rs * g[tid + 256] + beta[tid + 256];
}

// ---------------- softmax + argmax + prob write + token record ----------------
__global__ __launch_bounds__(256) void softmax_tok(
    const float* __restrict__ logits, float* __restrict__ probs,
    float* __restrict__ tokf, int* __restrict__ tok, int step)
{
    const int b = blockIdx.x;
    const float* row = logits + (size_t)b * V_;
    const int tid = threadIdx.x;
    __shared__ float smx[256];
    __shared__ int   sidx[256];

    float mx = -3.4e38f; int mi = 0;
    for (int v = tid; v < V_; v += 256) {
        float val = row[v];
        if (val > mx) { mx = val; mi = v; }
    }
    smx[tid] = mx; sidx[tid] = mi;
    __syncthreads();
    for (int o = 128; o; o >>= 1) {
        if (tid < o) {
            float om = smx[tid + o]; int oi = sidx[tid + o];
            if (om > smx[tid] || (om == smx[tid] && oi < sidx[tid])) {
                smx[tid] = om; sidx[tid] = oi;
            }
        }
        __syncthreads();
    }
    float m = smx[0];
    int amax = sidx[0];
    __syncthreads();

    float sum = 0.f;
    for (int v = tid; v < V_; v += 256) sum += expf(row[v] - m);
    smx[tid] = sum;
    __syncthreads();
    for (int o = 128; o; o >>= 1) {
        if (tid < o) smx[tid] += smx[tid + o];
        __syncthreads();
    }
    float inv = 1.0f / smx[0];

    for (int v = tid; v < V_; v += 256)
        probs[(size_t)b * V_ + v] = expf(row[v] - m) * inv;

    if (tid == 0) {
        tok[b] = amax;
        if (tokf) tokf[(size_t)b * T_ + step] = (float)amax;
    }
}

// ---------------- misc small kernels ----------------
__global__ void pe_init(float* __restrict__ pe)
{
    int t = blockIdx.x;
    for (int i = threadIdx.x; i < E_ / 2; i += 256) {
        float div = expf((float)(2 * i) * (-logf(10000.0f) / (float)E_));
        float arg = (float)t * div;
        pe[t * E_ + 2 * i]     = sinf(arg);
        pe[t * E_ + 2 * i + 1] = cosf(arg);
    }
}

__global__ void init_x(const float* __restrict__ emb, float* __restrict__ tb)
{
    int b = blockIdx.x;
    for (int e = threadIdx.x; e < E_; e += 256)
        tb[(size_t)b * E_ + e] = emb[(size_t)SOS_ * E_ + e];
}

__global__ void append_tok(const float* __restrict__ emb, float* __restrict__ tb,
                           const float* __restrict__ pe, const int* __restrict__ tok, int step)
{
    int b = blockIdx.x;
    int t = tok[b];
    size_t dst = ((size_t)(step + 1) * B_ + b) * E_;
    for (int e = threadIdx.x; e < E_; e += 256)
        tb[dst + e] = emb[(size_t)t * E_ + e] + pe[step * E_ + e];
}

__global__ void copy4(float4* __restrict__ dst, const float4* __restrict__ src)
{
    int i = blockIdx.x * 256 + threadIdx.x;
    dst[i] = src[i];
}

// ---------------- host-side GEMM dispatch ----------------
static inline void launch_gemm(const float* A, const float* W, const float* bias,
                               float* C, int M, int N, int K, int relu)
{
    int b128 = (M >> 7) * (N >> 7);
    if ((M % 128) == 0 && (N % 128) == 0 && b128 >= 120)
        gemm128<<<dim3(N >> 7, M >> 7), 256>>>(A, W, bias, C, M, N, K, relu);
    else
        gemm64<<<dim3(N >> 6, M >> 6), 128>>>(A, W, bias, C, M, N, K, relu);
}

// ---------------- launcher ----------------
extern "C" void kernel_launch(void* const* d_in, const int* in_sizes, int n_in,
                              void* d_out, int out_size)
{
    const float* cur      = (const float*)d_in[0];
    const float* emb      = (const float*)d_in[1];
    const float* sa_in_w  = (const float*)d_in[2];
    const float* sa_in_b  = (const float*)d_in[3];
    const float* sa_out_w = (const float*)d_in[4];
    const float* sa_out_b = (const float*)d_in[5];
    const float* ca_in_w  = (const float*)d_in[6];
    const float* ca_in_b  = (const float*)d_in[7];
    const float* ca_out_w = (const float*)d_in[8];
    const float* ca_out_b = (const float*)d_in[9];
    const float* ff1_w    = (const float*)d_in[10];
    const float* ff1_b    = (const float*)d_in[11];
    const float* ff2_w    = (const float*)d_in[12];
    const float* ff2_b    = (const float*)d_in[13];
    const float* ln_g     = (const float*)d_in[14];
    const float* ln_b     = (const float*)d_in[15];
    const float* out_w    = (const float*)d_in[16];
    const float* out_b    = (const float*)d_in[17];

    float *tb, *x, *qkv0, *qkv, *attn, *tmp, *cb, *hv, *pe, *logits;
    int* tok;
    cudaGetSymbolAddress((void**)&tb,     g_tb);
    cudaGetSymbolAddress((void**)&x,      g_x);
    cudaGetSymbolAddress((void**)&qkv0,   g_qkv0);
    cudaGetSymbolAddress((void**)&qkv,    g_qkv);
    cudaGetSymbolAddress((void**)&attn,   g_attn);
    cudaGetSymbolAddress((void**)&tmp,    g_tmp);
    cudaGetSymbolAddress((void**)&cb,     g_c);
    cudaGetSymbolAddress((void**)&hv,     g_hv);
    cudaGetSymbolAddress((void**)&pe,     g_pe);
    cudaGetSymbolAddress((void**)&logits, g_logits);
    cudaGetSymbolAddress((void**)&tok,    g_tok);

    float* outp = (float*)d_out;
    long long tok_elems = (long long)out_size - (long long)T_ * B_ * V_;
    float* tokf = (tok_elems > 0) ? outp : nullptr;
    float* probs_base = (tok_elems > 0) ? (outp + tok_elems) : outp;

    pe_init<<<T_, 256>>>(pe);
    init_x<<<B_, 256>>>(emb, tb);

    // Cross-attention collapses (kv seq len 1 => softmax == 1):
    // c[l][b] = ca_out_w[l] @ (ca_wv[l] @ cur_b + bv) + ca_out_b[l]
    for (int l = 0; l < L_; l++) {
        launch_gemm(cur, ca_in_w + ((size_t)l * 3 * E_ + 2 * E_) * E_,
                    ca_in_b + (size_t)l * 3 * E_ + 2 * E_, hv, B_, E_, E_, 0);
        launch_gemm(hv, ca_out_w + (size_t)l * E_ * E_, ca_out_b + (size_t)l * E_,
                    cb + (size_t)l * B_ * E_, B_, E_, E_, 0);
    }

    for (int i = 0; i < T_; i++) {
        const int S = i + 1;
        const int M = S * B_;

        // x = copy(tok_before[0:S])
        copy4<<<S * (B_ * E_ / 4 / 256), 256>>>((float4*)x, (const float4*)tb);

        for (int l = 0; l < L_; l++) {
            // QKV projection
            const float* qkv_src;
            if (l == 0) {
                // layer-0 input rows are immutable across steps: only new row
                launch_gemm(tb + (size_t)i * B_ * E_,
                            sa_in_w, sa_in_b,
                            qkv0 + (size_t)i * B_ * 3 * E_,
                            B_, 3 * E_, E_, 0);
                qkv_src = qkv0;
            } else {
                launch_gemm(x, sa_in_w + (size_t)l * 3 * E_ * E_,
                            sa_in_b + (size_t)l * 3 * E_,
                            qkv, M, 3 * E_, E_, 0);
                qkv_src = qkv;
            }
            self_attn<<<dim3(B_, H_), 256>>>(qkv_src, attn, S);
            launch_gemm(attn, sa_out_w + (size_t)l * E_ * E_,
                        sa_out_b + (size_t)l * E_, tmp, M, E_, E_, 0);
            // x = LN(x+tmp); x = LN(x + c[l])  (fused)
            ln2_add<<<M, 256>>>(x, tmp, cb + (size_t)l * B_ * E_,
                                ln_g + (size_t)(l * 3 + 0) * E_,
                                ln_b + (size_t)(l * 3 + 0) * E_,
                                ln_g + (size_t)(l * 3 + 1) * E_,
                                ln_b + (size_t)(l * 3 + 1) * E_);
            // fused feed-forward + residual + LN
            ff_fused<<<M, 256>>>(x,
                                 ff1_w + (size_t)l * F_ * E_, ff1_b + (size_t)l * F_,
                                 ff2_w + (size_t)l * E_ * F_, ff2_b + (size_t)l * E_,
                                 ln_g + (size_t)(l * 3 + 2) * E_,
                                 ln_b + (size_t)(l * 3 + 2) * E_);
        }

        // logits for last position, then softmax/argmax/probs
        launch_gemm(x + (size_t)(S - 1) * B_ * E_, out_w, out_b, logits,
                    B_, V_, E_, 0);
        softmax_tok<<<B_, 256>>>(logits, probs_base + (size_t)i * B_ * V_, tokf, tok, i);

        if (i + 1 < T_)
            append_tok<<<B_, 256>>>(emb, tb, pe, tok, i);
    }
}

// round 4
// speedup vs baseline: 2.0070x; 1.0010x over previous
#include <cuda_runtime.h>
#include <math.h>

#define E_  512
#define H_  8
#define HD_ 64
#define F_  32
#define L_  3
#define V_  32000
#define B_  128
#define T_  16
#define SOS_ 1

// ---------------- scratch (static device globals; no allocation) ----------------
__device__ float g_tb[T_*B_*E_];          // tok_before embeddings
__device__ float g_x[T_*B_*E_];           // working activations
__device__ float g_qkv0[T_*B_*3*E_];      // layer-0 QKV cache (rows immutable)
__device__ float g_qkv[T_*B_*3*E_];       // layers 1-2 QKV
__device__ float g_attn[T_*B_*E_];
__device__ float g_tmp[T_*B_*E_];
__device__ float g_c[L_*B_*E_];           // precomputed cross-attn constants
__device__ float g_hv[B_*E_];
__device__ float g_pe[T_*E_];
__device__ float g_logits[B_*V_];
__device__ int   g_tok[B_];

typedef unsigned long long ull;

// ---------------- packed fp32x2 helpers ----------------
__device__ __forceinline__ ull dupf(float f) {
    ull r; unsigned u = __float_as_uint(f);
    asm("mov.b64 %0, {%1, %1};" : "=l"(r) : "r"(u));
    return r;
}
__device__ __forceinline__ void ffma2(ull& d, ull a, ull b) {
    asm("fma.rn.f32x2 %0, %1, %2, %0;" : "+l"(d) : "l"(a), "l"(b));
}

// ================= GEMM 128x128 tile, f32x2, double-buffered =================
// C[M,N] = A[M,K] @ W[N,K]^T + bias. Requires M%128==0, N%128==0, K%8==0.
__global__ __launch_bounds__(256, 2) void gemm128(
    const float* __restrict__ A, const float* __restrict__ W,
    const float* __restrict__ bias, float* __restrict__ C,
    int M, int N, int K, int relu)
{
    __shared__ float As[2][8][128];
    __shared__ ull   Wd[2][8][128];

    const int m0 = blockIdx.y * 128;
    const int n0 = blockIdx.x * 128;
    const int tid = threadIdx.x;
    const int tm = tid >> 4;          // 0..15 -> 8 M rows (4 pairs)
    const int tn = tid & 15;          // 0..15 -> 8 N cols (stride 16)
    const int lrow = tid >> 1;        // 0..127
    const int lk   = (tid & 1) * 4;   // 0 or 4

    const float* Aptr = A + (size_t)(m0 + lrow) * K + lk;
    const float* Wptr = W + (size_t)(n0 + lrow) * K + lk;

    ull acc[4][8];
#pragma unroll
    for (int q = 0; q < 4; q++)
#pragma unroll
        for (int j = 0; j < 8; j++) acc[q][j] = 0ull;

    float4 av = *reinterpret_cast<const float4*>(Aptr);
    float4 wv = *reinterpret_cast<const float4*>(Wptr);
    As[0][lk+0][lrow] = av.x; As[0][lk+1][lrow] = av.y;
    As[0][lk+2][lrow] = av.z; As[0][lk+3][lrow] = av.w;
    Wd[0][lk+0][lrow] = dupf(wv.x); Wd[0][lk+1][lrow] = dupf(wv.y);
    Wd[0][lk+2][lrow] = dupf(wv.z); Wd[0][lk+3][lrow] = dupf(wv.w);
    __syncthreads();

    const int NT = K >> 3;
    int buf = 0;
    for (int t = 0; t < NT; t++) {
        if (t + 1 < NT) {
            av = *reinterpret_cast<const float4*>(Aptr + (t + 1) * 8);
            wv = *reinterpret_cast<const float4*>(Wptr + (t + 1) * 8);
        }
#pragma unroll
        for (int kk = 0; kk < 8; kk++) {
            ulonglong2 av0 = *reinterpret_cast<const ulonglong2*>(&As[buf][kk][tm * 8]);
            ulonglong2 av1 = *reinterpret_cast<const ulonglong2*>(&As[buf][kk][tm * 8 + 4]);
            ull a2[4] = { av0.x, av0.y, av1.x, av1.y };
            ull w2[8];
#pragma unroll
            for (int j = 0; j < 8; j++) w2[j] = Wd[buf][kk][tn + 16 * j];
#pragma unroll
            for (int q = 0; q < 4; q++)
#pragma unroll
                for (int j = 0; j < 8; j++) ffma2(acc[q][j], a2[q], w2[j]);
        }
        if (t + 1 < NT) {
            buf ^= 1;
            As[buf][lk+0][lrow] = av.x; As[buf][lk+1][lrow] = av.y;
            As[buf][lk+2][lrow] = av.z; As[buf][lk+3][lrow] = av.w;
            Wd[buf][lk+0][lrow] = dupf(wv.x); Wd[buf][lk+1][lrow] = dupf(wv.y);
            Wd[buf][lk+2][lrow] = dupf(wv.z); Wd[buf][lk+3][lrow] = dupf(wv.w);
            __syncthreads();
        }
    }

#pragma unroll
    for (int q = 0; q < 4; q++) {
        int m = m0 + tm * 8 + 2 * q;
#pragma unroll
        for (int j = 0; j < 8; j++) {
            int n = n0 + tn + 16 * j;
            float2 v = *reinterpret_cast<float2*>(&acc[q][j]);
            float c0 = v.x + bias[n];
            float c1 = v.y + bias[n];
            if (relu) { c0 = fmaxf(c0, 0.f); c1 = fmaxf(c1, 0.f); }
            C[(size_t)m * N + n]       = c0;
            C[(size_t)(m + 1) * N + n] = c1;
        }
    }
}

// ================= GEMM 64x64 tile, 256 threads, BK=16 =================
// Requires M%64==0, N%64==0, K%16==0.
__global__ __launch_bounds__(256) void gemm64(
    const float* __restrict__ A, const float* __restrict__ W,
    const float* __restrict__ bias, float* __restrict__ C,
    int M, int N, int K, int relu)
{
    __shared__ float As[2][16][66];
    __shared__ ull   Wd[2][16][66];

    const int m0 = blockIdx.y * 64;
    const int n0 = blockIdx.x * 64;
    const int tid = threadIdx.x;
    const int tm = tid >> 4;          // 0..15 -> rows tm*4..tm*4+3 (2 pairs)
    const int tn = tid & 15;          // 0..15 -> cols tn+16j, j=0..3
    const int lrow = tid >> 2;        // 0..63
    const int lk   = (tid & 3) * 4;   // 0,4,8,12

    const float* Aptr = A + (size_t)(m0 + lrow) * K + lk;
    const float* Wptr = W + (size_t)(n0 + lrow) * K + lk;

    ull acc[2][4];
#pragma unroll
    for (int q = 0; q < 2; q++)
#pragma unroll
        for (int j = 0; j < 4; j++) acc[q][j] = 0ull;

    float4 av = *reinterpret_cast<const float4*>(Aptr);
    float4 wv = *reinterpret_cast<const float4*>(Wptr);
    As[0][lk+0][lrow] = av.x; As[0][lk+1][lrow] = av.y;
    As[0][lk+2][lrow] = av.z; As[0][lk+3][lrow] = av.w;
    Wd[0][lk+0][lrow] = dupf(wv.x); Wd[0][lk+1][lrow] = dupf(wv.y);
    Wd[0][lk+2][lrow] = dupf(wv.z); Wd[0][lk+3][lrow] = dupf(wv.w);
    __syncthreads();

    const int NT = K >> 4;
    int buf = 0;
    for (int t = 0; t < NT; t++) {
        if (t + 1 < NT) {
            av = *reinterpret_cast<const float4*>(Aptr + (t + 1) * 16);
            wv = *reinterpret_cast<const float4*>(Wptr + (t + 1) * 16);
        }
#pragma unroll
        for (int kk = 0; kk < 16; kk++) {
            ull a2[2], w2[4];
            a2[0] = *reinterpret_cast<const ull*>(&As[buf][kk][tm * 4]);
            a2[1] = *reinterpret_cast<const ull*>(&As[buf][kk][tm * 4 + 2]);
#pragma unroll
            for (int j = 0; j < 4; j++) w2[j] = Wd[buf][kk][tn + 16 * j];
#pragma unroll
            for (int q = 0; q < 2; q++)
#pragma unroll
                for (int j = 0; j < 4; j++) ffma2(acc[q][j], a2[q], w2[j]);
        }
        if (t + 1 < NT) {
            buf ^= 1;
            As[buf][lk+0][lrow] = av.x; As[buf][lk+1][lrow] = av.y;
            As[buf][lk+2][lrow] = av.z; As[buf][lk+3][lrow] = av.w;
            Wd[buf][lk+0][lrow] = dupf(wv.x); Wd[buf][lk+1][lrow] = dupf(wv.y);
            Wd[buf][lk+2][lrow] = dupf(wv.z); Wd[buf][lk+3][lrow] = dupf(wv.w);
            __syncthreads();
        }
    }

#pragma unroll
    for (int q = 0; q < 2; q++) {
        int m = m0 + tm * 4 + 2 * q;
#pragma unroll
        for (int j = 0; j < 4; j++) {
            int n = n0 + tn + 16 * j;
            float2 v = *reinterpret_cast<float2*>(&acc[q][j]);
            float c0 = v.x + bias[n];
            float c1 = v.y + bias[n];
            if (relu) { c0 = fmaxf(c0, 0.f); c1 = fmaxf(c1, 0.f); }
            C[(size_t)m * N + n]       = c0;
            C[(size_t)(m + 1) * N + n] = c1;
        }
    }
}

// ================= GEMM 32x32 tile, 256 threads, BK=32 (max fill) =================
// Requires M%32==0, N%32==0, K%32==0.
__global__ __launch_bounds__(256) void gemm32(
    const float* __restrict__ A, const float* __restrict__ W,
    const float* __restrict__ bias, float* __restrict__ C,
    int M, int N, int K, int relu)
{
    __shared__ float As[2][32][34];
    __shared__ ull   Wd[2][32][34];

    const int m0 = blockIdx.y * 32;
    const int n0 = blockIdx.x * 32;
    const int tid = threadIdx.x;
    const int tm = tid >> 4;          // 0..15 -> pair rows 2tm, 2tm+1
    const int tn = tid & 15;          // 0..15 -> cols tn, tn+16
    const int lrow = tid >> 3;        // 0..31
    const int lk   = (tid & 7) * 4;   // 0..28

    const float* Aptr = A + (size_t)(m0 + lrow) * K + lk;
    const float* Wptr = W + (size_t)(n0 + lrow) * K + lk;

    ull acc[2] = { 0ull, 0ull };

    float4 av = *reinterpret_cast<const float4*>(Aptr);
    float4 wv = *reinterpret_cast<const float4*>(Wptr);
    As[0][lk+0][lrow] = av.x; As[0][lk+1][lrow] = av.y;
    As[0][lk+2][lrow] = av.z; As[0][lk+3][lrow] = av.w;
    Wd[0][lk+0][lrow] = dupf(wv.x); Wd[0][lk+1][lrow] = dupf(wv.y);
    Wd[0][lk+2][lrow] = dupf(wv.z); Wd[0][lk+3][lrow] = dupf(wv.w);
    __syncthreads();

    const int NT = K >> 5;
    int buf = 0;
    for (int t = 0; t < NT; t++) {
        if (t + 1 < NT) {
            av = *reinterpret_cast<const float4*>(Aptr + (t + 1) * 32);
            wv = *reinterpret_cast<const float4*>(Wptr + (t + 1) * 32);
        }
#pragma unroll
        for (int kk = 0; kk < 32; kk++) {
            ull a2 = *reinterpret_cast<const ull*>(&As[buf][kk][tm * 2]);
            ffma2(acc[0], a2, Wd[buf][kk][tn]);
            ffma2(acc[1], a2, Wd[buf][kk][tn + 16]);
        }
        if (t + 1 < NT) {
            buf ^= 1;
            As[buf][lk+0][lrow] = av.x; As[buf][lk+1][lrow] = av.y;
            As[buf][lk+2][lrow] = av.z; As[buf][lk+3][lrow] = av.w;
            Wd[buf][lk+0][lrow] = dupf(wv.x); Wd[buf][lk+1][lrow] = dupf(wv.y);
            Wd[buf][lk+2][lrow] = dupf(wv.z); Wd[buf][lk+3][lrow] = dupf(wv.w);
            __syncthreads();
        }
    }

    int m = m0 + tm * 2;
#pragma unroll
    for (int j = 0; j < 2; j++) {
        int n = n0 + tn + 16 * j;
        float2 v = *reinterpret_cast<float2*>(&acc[j]);
        float c0 = v.x + bias[n];
        float c1 = v.y + bias[n];
        if (relu) { c0 = fmaxf(c0, 0.f); c1 = fmaxf(c1, 0.f); }
        C[(size_t)m * N + n]       = c0;
        C[(size_t)(m + 1) * N + n] = c1;
    }
}

// ---------------- block reduction helper (256 threads) ----------------
__device__ __forceinline__ float blocksum256(float v)
{
    __shared__ float red[8];
    for (int o = 16; o; o >>= 1) v += __shfl_down_sync(0xffffffffu, v, o);
    if ((threadIdx.x & 31) == 0) red[threadIdx.x >> 5] = v;
    __syncthreads();
    if (threadIdx.x < 32) {
        float s = (threadIdx.x < 8) ? red[threadIdx.x] : 0.f;
        for (int o = 4; o; o >>= 1) s += __shfl_down_sync(0xffffffffu, s, o);
        if (threadIdx.x == 0) red[0] = s;
    }
    __syncthreads();
    float r = red[0];
    __syncthreads();
    return r;
}

// ---------------- self-attention (S<=16, per (b,h) block) ----------------
__global__ __launch_bounds__(256) void self_attn(
    const float* __restrict__ qkv, float* __restrict__ out, int S)
{
    const int b = blockIdx.x, h = blockIdx.y;
    __shared__ float q[T_][HD_ + 1], k[T_][HD_ + 1], v[T_][HD_ + 1];
    __shared__ float p[T_][T_ + 1];
    const int tid = threadIdx.x;

    for (int idx = tid; idx < S * HD_; idx += 256) {
        int s = idx >> 6, d = idx & 63;
        size_t base = ((size_t)(s * B_ + b)) * (3 * E_) + h * HD_ + d;
        q[s][d] = qkv[base];
        k[s][d] = qkv[base + E_];
        v[s][d] = qkv[base + 2 * E_];
    }
    __syncthreads();

    for (int idx = tid; idx < S * S; idx += 256) {
        int sq = idx / S, sk = idx - sq * S;
        float acc = 0.f;
#pragma unroll
        for (int d = 0; d < HD_; d++) acc = fmaf(q[sq][d], k[sk][d], acc);
        p[sq][sk] = acc * 0.125f;
    }
    __syncthreads();

    if (tid < S) {
        float mx = -3.4e38f;
        for (int sk = 0; sk < S; sk++) mx = fmaxf(mx, p[tid][sk]);
        float sum = 0.f;
        for (int sk = 0; sk < S; sk++) { float e = expf(p[tid][sk] - mx); p[tid][sk] = e; sum += e; }
        float inv = 1.f / sum;
        for (int sk = 0; sk < S; sk++) p[tid][sk] *= inv;
    }
    __syncthreads();

    for (int idx = tid; idx < S * HD_; idx += 256) {
        int s = idx >> 6, d = idx & 63;
        float acc = 0.f;
        for (int sk = 0; sk < S; sk++) acc = fmaf(p[s][sk], v[sk][d], acc);
        out[((size_t)(s * B_ + b)) * E_ + h * HD_ + d] = acc;
    }
}

// -------- fused: x = LN(x+add, g0,b0); x = LN(x + c[b], g1,b1) --------
__global__ __launch_bounds__(256) void ln2_add(
    float* __restrict__ x, const float* __restrict__ add,
    const float* __restrict__ c,
    const float* __restrict__ g0, const float* __restrict__ b0,
    const float* __restrict__ g1, const float* __restrict__ b1)
{
    const int row = blockIdx.x;
    const int bb  = row & (B_ - 1);
    const int tid = threadIdx.x;
    float* xr = x + (size_t)row * E_;
    const float* ar = add + (size_t)row * E_;
    const float* cr = c + (size_t)bb * E_;

    float v0 = xr[tid] + ar[tid];
    float v1 = xr[tid + 256] + ar[tid + 256];

    float mean = blocksum256(v0 + v1) * (1.0f / (float)E_);
    float d0 = v0 - mean, d1 = v1 - mean;
    float var = blocksum256(d0 * d0 + d1 * d1) * (1.0f / (float)E_);
    float rs = rsqrtf(var + 1e-5f);
    float y0 = d0 * rs * g0[tid]       + b0[tid]       + cr[tid];
    float y1 = d1 * rs * g0[tid + 256] + b0[tid + 256] + cr[tid + 256];

    float mean2 = blocksum256(y0 + y1) * (1.0f / (float)E_);
    float e0 = y0 - mean2, e1 = y1 - mean2;
    float var2 = blocksum256(e0 * e0 + e1 * e1) * (1.0f / (float)E_);
    float rs2 = rsqrtf(var2 + 1e-5f);
    xr[tid]       = e0 * rs2 * g1[tid]       + b1[tid];
    xr[tid + 256] = e1 * rs2 * g1[tid + 256] + b1[tid + 256];
}

// -------- fused FF: x = LN(x + ff2(relu(ff1(x)))), one row per block --------
__global__ __launch_bounds__(256) void ff_fused(
    float* __restrict__ x,
    const float* __restrict__ w1, const float* __restrict__ b1,
    const float* __restrict__ w2, const float* __restrict__ b2,
    const float* __restrict__ g, const float* __restrict__ beta)
{
    const int row = blockIdx.x;
    const int tid = threadIdx.x;
    __shared__ float xs[E_];
    __shared__ float hs[F_];
    float* xr = x + (size_t)row * E_;

    xs[tid] = xr[tid];
    xs[tid + 256] = xr[tid + 256];
    __syncthreads();

    const int u = tid >> 3, l = tid & 7;
    const float4* w4  = reinterpret_cast<const float4*>(w1 + (size_t)u * E_);
    const float4* xs4 = reinterpret_cast<const float4*>(xs);
    float p = 0.f;
#pragma unroll
    for (int k4 = 0; k4 < 16; k4++) {
        float4 wv = w4[l + 8 * k4];
        float4 xv = xs4[l + 8 * k4];
        p += wv.x * xv.x + wv.y * xv.y + wv.z * xv.z + wv.w * xv.w;
    }
    for (int o = 4; o; o >>= 1) p += __shfl_down_sync(0xffffffffu, p, o, 8);
    if (l == 0) hs[u] = fmaxf(p + b1[u], 0.f);
    __syncthreads();

    float a0 = b2[tid]       + xs[tid];
    float a1 = b2[tid + 256] + xs[tid + 256];
    const float4* w20 = reinterpret_cast<const float4*>(w2 + (size_t)tid * F_);
    const float4* w21 = reinterpret_cast<const float4*>(w2 + (size_t)(tid + 256) * F_);
#pragma unroll
    for (int c4 = 0; c4 < 8; c4++) {
        float4 wa = w20[c4], wb = w21[c4];
        a0 = fmaf(hs[4*c4+0], wa.x, a0); a0 = fmaf(hs[4*c4+1], wa.y, a0);
        a0 = fmaf(hs[4*c4+2], wa.z, a0); a0 = fmaf(hs[4*c4+3], wa.w, a0);
        a1 = fmaf(hs[4*c4+0], wb.x, a1); a1 = fmaf(hs[4*c4+1], wb.y, a1);
        a1 = fmaf(hs[4*c4+2], wb.z, a1); a1 = fmaf(hs[4*c4+3], wb.w, a1);
    }

    float mean = blocksum256(a0 + a1) * (1.0f / (float)E_);
    float d0 = a0 - mean, d1 = a1 - mean;
    float var = blocksum256(d0 * d0 + d1 * d1) * (1.0f / (float)E_);
    float rs = rsqrtf(var + 1e-5f);
    xr[tid]       = d0 * rs * g[tid]       + beta[tid];
    xr[tid + 256] = d1 * rs * g[tid + 256] + beta[tid + 256];
}

// ------- softmax + argmax + probs (online max/sum: 2 passes over row) -------
__global__ __launch_bounds__(256) void softmax_tok(
    const float* __restrict__ logits, float* __restrict__ probs,
    float* __restrict__ tokf, int* __restrict__ tok, int step)
{
    const int b = blockIdx.x;
    const float* row = logits + (size_t)b * V_;
    const int tid = threadIdx.x;
    __shared__ float smx[256], ssm[256];
    __shared__ int   sidx[256];

    // online (max,sum) per thread
    float mx = -3.4e38f, sm = 0.f; int mi = 0;
    for (int v = tid; v < V_; v += 256) {
        float val = row[v];
        if (val > mx) { sm = sm * expf(mx - val) + 1.f; mx = val; mi = v; }
        else          { sm += expf(val - mx); }
    }
    smx[tid] = mx; ssm[tid] = sm; sidx[tid] = mi;
    __syncthreads();
    for (int o = 128; o; o >>= 1) {
        if (tid < o) {
            float om = smx[tid + o], os = ssm[tid + o]; int oi = sidx[tid + o];
            float cm = smx[tid],     cs = ssm[tid];     int ci = sidx[tid];
            float nm = fmaxf(om, cm);
            ssm[tid] = cs * expf(cm - nm) + os * expf(om - nm);
            smx[tid] = nm;
            sidx[tid] = (om > cm || (om == cm && oi < ci)) ? oi : ci;
        }
        __syncthreads();
    }
    float m = smx[0];
    float inv = 1.0f / ssm[0];
    int amax = sidx[0];

    for (int v = tid; v < V_; v += 256)
        probs[(size_t)b * V_ + v] = expf(row[v] - m) * inv;

    if (tid == 0) {
        tok[b] = amax;
        if (tokf) tokf[(size_t)b * T_ + step] = (float)amax;
    }
}

// ---------------- misc small kernels ----------------
__global__ void pe_init(float* __restrict__ pe)
{
    int t = blockIdx.x;
    for (int i = threadIdx.x; i < E_ / 2; i += 256) {
        float div = expf((float)(2 * i) * (-logf(10000.0f) / (float)E_));
        float arg = (float)t * div;
        pe[t * E_ + 2 * i]     = sinf(arg);
        pe[t * E_ + 2 * i + 1] = cosf(arg);
    }
}

__global__ void init_x(const float* __restrict__ emb, float* __restrict__ tb)
{
    int b = blockIdx.x;
    for (int e = threadIdx.x; e < E_; e += 256)
        tb[(size_t)b * E_ + e] = emb[(size_t)SOS_ * E_ + e];
}

__global__ void append_tok(const float* __restrict__ emb, float* __restrict__ tb,
                           const float* __restrict__ pe, const int* __restrict__ tok, int step)
{
    int b = blockIdx.x;
    int t = tok[b];
    size_t dst = ((size_t)(step + 1) * B_ + b) * E_;
    for (int e = threadIdx.x; e < E_; e += 256)
        tb[dst + e] = emb[(size_t)t * E_ + e] + pe[step * E_ + e];
}

__global__ void copy4(float4* __restrict__ dst, const float4* __restrict__ src)
{
    int i = blockIdx.x * 256 + threadIdx.x;
    dst[i] = src[i];
}

// ---------------- host-side GEMM dispatch (maximize chip fill) ----------------
static inline void launch_gemm(const float* A, const float* W, const float* bias,
                               float* C, int M, int N, int K, int relu)
{
    long long b128 = (long long)(M >> 7) * (N >> 7);
    long long b64  = (long long)(M >> 6) * (N >> 6);
    if ((M % 128) == 0 && (N % 128) == 0 && b128 >= 120)
        gemm128<<<dim3(N >> 7, M >> 7), 256>>>(A, W, bias, C, M, N, K, relu);
    else if ((M % 64) == 0 && (N % 64) == 0 && b64 >= 120 && (K % 16) == 0)
        gemm64<<<dim3(N >> 6, M >> 6), 256>>>(A, W, bias, C, M, N, K, relu);
    else
        gemm32<<<dim3(N >> 5, M >> 5), 256>>>(A, W, bias, C, M, N, K, relu);
}

// ---------------- launcher ----------------
extern "C" void kernel_launch(void* const* d_in, const int* in_sizes, int n_in,
                              void* d_out, int out_size)
{
    const float* cur      = (const float*)d_in[0];
    const float* emb      = (const float*)d_in[1];
    const float* sa_in_w  = (const float*)d_in[2];
    const float* sa_in_b  = (const float*)d_in[3];
    const float* sa_out_w = (const float*)d_in[4];
    const float* sa_out_b = (const float*)d_in[5];
    const float* ca_in_w  = (const float*)d_in[6];
    const float* ca_in_b  = (const float*)d_in[7];
    const float* ca_out_w = (const float*)d_in[8];
    const float* ca_out_b = (const float*)d_in[9];
    const float* ff1_w    = (const float*)d_in[10];
    const float* ff1_b    = (const float*)d_in[11];
    const float* ff2_w    = (const float*)d_in[12];
    const float* ff2_b    = (const float*)d_in[13];
    const float* ln_g     = (const float*)d_in[14];
    const float* ln_b     = (const float*)d_in[15];
    const float* out_w    = (const float*)d_in[16];
    const float* out_b    = (const float*)d_in[17];

    float *tb, *x, *qkv0, *qkv, *attn, *tmp, *cb, *hv, *pe, *logits;
    int* tok;
    cudaGetSymbolAddress((void**)&tb,     g_tb);
    cudaGetSymbolAddress((void**)&x,      g_x);
    cudaGetSymbolAddress((void**)&qkv0,   g_qkv0);
    cudaGetSymbolAddress((void**)&qkv,    g_qkv);
    cudaGetSymbolAddress((void**)&attn,   g_attn);
    cudaGetSymbolAddress((void**)&tmp,    g_tmp);
    cudaGetSymbolAddress((void**)&cb,     g_c);
    cudaGetSymbolAddress((void**)&hv,     g_hv);
    cudaGetSymbolAddress((void**)&pe,     g_pe);
    cudaGetSymbolAddress((void**)&logits, g_logits);
    cudaGetSymbolAddress((void**)&tok,    g_tok);

    float* outp = (float*)d_out;
    long long tok_elems = (long long)out_size - (long long)T_ * B_ * V_;
    float* tokf = (tok_elems > 0) ? outp : nullptr;
    float* probs_base = (tok_elems > 0) ? (outp + tok_elems) : outp;

    pe_init<<<T_, 256>>>(pe);
    init_x<<<B_, 256>>>(emb, tb);

    // Cross-attention collapses (kv seq len 1 => softmax == 1):
    // c[l][b] = ca_out_w[l] @ (ca_wv[l] @ cur_b + bv) + ca_out_b[l]
    for (int l = 0; l < L_; l++) {
        launch_gemm(cur, ca_in_w + ((size_t)l * 3 * E_ + 2 * E_) * E_,
                    ca_in_b + (size_t)l * 3 * E_ + 2 * E_, hv, B_, E_, E_, 0);
        launch_gemm(hv, ca_out_w + (size_t)l * E_ * E_, ca_out_b + (size_t)l * E_,
                    cb + (size_t)l * B_ * E_, B_, E_, E_, 0);
    }

    for (int i = 0; i < T_; i++) {
        const int S = i + 1;
        const int M = S * B_;

        // x = copy(tok_before[0:S])
        copy4<<<S * (B_ * E_ / 4 / 256), 256>>>((float4*)x, (const float4*)tb);

        for (int l = 0; l < L_; l++) {
            const float* qkv_src;
            if (l == 0) {
                // layer-0 input rows are immutable across steps: only new row
                launch_gemm(tb + (size_t)i * B_ * E_,
                            sa_in_w, sa_in_b,
                            qkv0 + (size_t)i * B_ * 3 * E_,
                            B_, 3 * E_, E_, 0);
                qkv_src = qkv0;
            } else {
                launch_gemm(x, sa_in_w + (size_t)l * 3 * E_ * E_,
                            sa_in_b + (size_t)l * 3 * E_,
                            qkv, M, 3 * E_, E_, 0);
                qkv_src = qkv;
            }
            self_attn<<<dim3(B_, H_), 256>>>(qkv_src, attn, S);
            launch_gemm(attn, sa_out_w + (size_t)l * E_ * E_,
                        sa_out_b + (size_t)l * E_, tmp, M, E_, E_, 0);
            ln2_add<<<M, 256>>>(x, tmp, cb + (size_t)l * B_ * E_,
                                ln_g + (size_t)(l * 3 + 0) * E_,
                                ln_b + (size_t)(l * 3 + 0) * E_,
                                ln_g + (size_t)(l * 3 + 1) * E_,
                                ln_b + (size_t)(l * 3 + 1) * E_);
            ff_fused<<<M, 256>>>(x,
                                 ff1_w + (size_t)l * F_ * E_, ff1_b + (size_t)l * F_,
                                 ff2_w + (size_t)l * E_ * F_, ff2_b + (size_t)l * E_,
                                 ln_g + (size_t)(l * 3 + 2) * E_,
                                 ln_b + (size_t)(l * 3 + 2) * E_);
        }

        // logits for last position, then softmax/argmax/probs
        launch_gemm(x + (size_t)(S - 1) * B_ * E_, out_w, out_b, logits,
                    B_, V_, E_, 0);
        softmax_tok<<<B_, 256>>>(logits, probs_base + (size_t)i * B_ * V_, tokf, tok, i);

        if (i + 1 < T_)
            append_tok<<<B_, 256>>>(emb, tb, pe, tok, i);
    }
}

// round 5
// speedup vs baseline: 2.4302x; 1.2108x over previous
#include <cuda_runtime.h>
#include <math.h>

#define E_  512
#define H_  8
#define HD_ 64
#define F_  32
#define L_  3
#define V_  32000
#define B_  128
#define T_  16
#define SOS_ 1

// ---------------- scratch (static device globals; no allocation) ----------------
__device__ float g_tb[T_*B_*E_];          // tok_before embeddings
__device__ float g_x[T_*B_*E_];           // working activations
__device__ float g_qkv0[T_*B_*3*E_];      // layer-0 QKV cache (rows immutable)
__device__ float g_qkv[T_*B_*3*E_];       // layers 1-2 QKV
__device__ float g_attn[T_*B_*E_];
__device__ float g_tmp[T_*B_*E_];
__device__ float g_c[L_*B_*E_];           // precomputed cross-attn constants
__device__ float g_hv[B_*E_];
__device__ float g_pe[T_*E_];
__device__ float g_logits[B_*V_];
__device__ float g_sk[2*1024*1024];       // split-K partials

typedef unsigned long long ull;

// ---------------- packed fp32x2 helpers ----------------
__device__ __forceinline__ ull dupf(float f) {
    ull r; unsigned u = __float_as_uint(f);
    asm("mov.b64 %0, {%1, %1};" : "=l"(r) : "r"(u));
    return r;
}
__device__ __forceinline__ void ffma2(ull& d, ull a, ull b) {
    asm("fma.rn.f32x2 %0, %1, %2, %0;" : "+l"(d) : "l"(a), "l"(b));
}

// ========== GEMM 128x128, BK=16, 8x8 microtile, W reg-dup (1 B/MAC) ==========
// C[M,N] = A[M,K] @ W[N,K]^T + bias. Requires M%128==0, N%128==0, K%32==0.
__global__ __launch_bounds__(256, 2) void gemm128(
    const float* __restrict__ A, const float* __restrict__ W,
    const float* __restrict__ bias, float* __restrict__ C,
    int M, int N, int K, int relu)
{
    __shared__ float As[2][16][132];
    __shared__ float Ws[2][16][132];

    const int m0 = blockIdx.y * 128, n0 = blockIdx.x * 128;
    const int tid = threadIdx.x;
    const int tm = tid >> 4, tn = tid & 15;
    const int lrow = tid >> 1, lk = (tid & 1) * 8;

    const float* Ap = A + (size_t)(m0 + lrow) * K + lk;
    const float* Wp = W + (size_t)(n0 + lrow) * K + lk;

    ull acc[4][8];
#pragma unroll
    for (int q = 0; q < 4; q++)
#pragma unroll
        for (int j = 0; j < 8; j++) acc[q][j] = 0ull;

    float4 a0 = *(const float4*)Ap, a1 = *(const float4*)(Ap + 4);
    float4 w0 = *(const float4*)Wp, w1 = *(const float4*)(Wp + 4);
#pragma unroll
    for (int i = 0; i < 4; i++) {
        As[0][lk + i][lrow]     = (&a0.x)[i];
        As[0][lk + 4 + i][lrow] = (&a1.x)[i];
        Ws[0][lk + i][lrow]     = (&w0.x)[i];
        Ws[0][lk + 4 + i][lrow] = (&w1.x)[i];
    }
    __syncthreads();

    const int NT = K >> 4;
    int buf = 0;
    for (int t = 0; t < NT; t++) {
        if (t + 1 < NT) {
            a0 = *(const float4*)(Ap + (t + 1) * 16);
            a1 = *(const float4*)(Ap + (t + 1) * 16 + 4);
            w0 = *(const float4*)(Wp + (t + 1) * 16);
            w1 = *(const float4*)(Wp + (t + 1) * 16 + 4);
        }
#pragma unroll
        for (int kk = 0; kk < 16; kk++) {
            ulonglong2 ap0 = *(const ulonglong2*)&As[buf][kk][tm * 8];
            ulonglong2 ap1 = *(const ulonglong2*)&As[buf][kk][tm * 8 + 4];
            ull a2[4] = { ap0.x, ap0.y, ap1.x, ap1.y };
            float4 wv0 = *(const float4*)&Ws[buf][kk][tn * 8];
            float4 wv1 = *(const float4*)&Ws[buf][kk][tn * 8 + 4];
            ull w2[8] = { dupf(wv0.x), dupf(wv0.y), dupf(wv0.z), dupf(wv0.w),
                          dupf(wv1.x), dupf(wv1.y), dupf(wv1.z), dupf(wv1.w) };
#pragma unroll
            for (int q = 0; q < 4; q++)
#pragma unroll
                for (int j = 0; j < 8; j++) ffma2(acc[q][j], a2[q], w2[j]);
        }
        if (t + 1 < NT) {
            buf ^= 1;
#pragma unroll
            for (int i = 0; i < 4; i++) {
                As[buf][lk + i][lrow]     = (&a0.x)[i];
                As[buf][lk + 4 + i][lrow] = (&a1.x)[i];
                Ws[buf][lk + i][lrow]     = (&w0.x)[i];
                Ws[buf][lk + 4 + i][lrow] = (&w1.x)[i];
            }
            __syncthreads();
        }
    }

    const float4 bA = *(const float4*)&bias[n0 + tn * 8];
    const float4 bB = *(const float4*)&bias[n0 + tn * 8 + 4];
#pragma unroll
    for (int q = 0; q < 4; q++) {
        int m = m0 + tm * 8 + 2 * q;
        float4 r0a, r0b, r1a, r1b;
#pragma unroll
        for (int j = 0; j < 4; j++) {
            float2 vA = *reinterpret_cast<float2*>(&acc[q][j]);
            float2 vB = *reinterpret_cast<float2*>(&acc[q][j + 4]);
            (&r0a.x)[j] = vA.x + (&bA.x)[j];
            (&r1a.x)[j] = vA.y + (&bA.x)[j];
            (&r0b.x)[j] = vB.x + (&bB.x)[j];
            (&r1b.x)[j] = vB.y + (&bB.x)[j];
        }
        if (relu) {
#pragma unroll
            for (int j = 0; j < 4; j++) {
                (&r0a.x)[j] = fmaxf((&r0a.x)[j], 0.f);
                (&r1a.x)[j] = fmaxf((&r1a.x)[j], 0.f);
                (&r0b.x)[j] = fmaxf((&r0b.x)[j], 0.f);
                (&r1b.x)[j] = fmaxf((&r1b.x)[j], 0.f);
            }
        }
        float* Cr0 = C + (size_t)m * N + n0 + tn * 8;
        float* Cr1 = Cr0 + N;
        *(float4*)Cr0 = r0a; *(float4*)(Cr0 + 4) = r0b;
        *(float4*)Cr1 = r1a; *(float4*)(Cr1 + 4) = r1b;
    }
}

// ========== GEMM 64x64, BK=16, 4x4 microtile, optional split-K ==========
// Requires M%64==0, N%64==0, (K/nsplit)%16==0.
__global__ __launch_bounds__(256) void gemm64(
    const float* __restrict__ A, const float* __restrict__ W,
    const float* __restrict__ bias, float* __restrict__ C,
    float* __restrict__ part,
    int M, int N, int K, int relu, int nsplit)
{
    __shared__ float As[2][16][68];
    __shared__ float Ws[2][16][68];

    const int m0 = blockIdx.y * 64, n0 = blockIdx.x * 64;
    const int kz = blockIdx.z;
    const int Kc = K / nsplit, kb = kz * Kc;
    const int tid = threadIdx.x;
    const int tm = tid >> 4, tn = tid & 15;
    const int lrow = tid >> 2, lk = (tid & 3) * 4;

    const float* Ap = A + (size_t)(m0 + lrow) * K + kb + lk;
    const float* Wp = W + (size_t)(n0 + lrow) * K + kb + lk;

    ull acc[2][4];
#pragma unroll
    for (int q = 0; q < 2; q++)
#pragma unroll
        for (int j = 0; j < 4; j++) acc[q][j] = 0ull;

    float4 av = *(const float4*)Ap;
    float4 wv = *(const float4*)Wp;
#pragma unroll
    for (int i = 0; i < 4; i++) {
        As[0][lk + i][lrow] = (&av.x)[i];
        Ws[0][lk + i][lrow] = (&wv.x)[i];
    }
    __syncthreads();

    const int NT = Kc >> 4;
    int buf = 0;
    for (int t = 0; t < NT; t++) {
        if (t + 1 < NT) {
            av = *(const float4*)(Ap + (t + 1) * 16);
            wv = *(const float4*)(Wp + (t + 1) * 16);
        }
#pragma unroll
        for (int kk = 0; kk < 16; kk++) {
            ulonglong2 ap = *(const ulonglong2*)&As[buf][kk][tm * 4];
            float4 w = *(const float4*)&Ws[buf][kk][tn * 4];
            ull w2[4] = { dupf(w.x), dupf(w.y), dupf(w.z), dupf(w.w) };
#pragma unroll
            for (int j = 0; j < 4; j++) {
                ffma2(acc[0][j], ap.x, w2[j]);
                ffma2(acc[1][j], ap.y, w2[j]);
            }
        }
        if (t + 1 < NT) {
            buf ^= 1;
#pragma unroll
            for (int i = 0; i < 4; i++) {
                As[buf][lk + i][lrow] = (&av.x)[i];
                Ws[buf][lk + i][lrow] = (&wv.x)[i];
            }
            __syncthreads();
        }
    }

    if (nsplit == 1) {
        const float4 bv = *(const float4*)&bias[n0 + tn * 4];
#pragma unroll
        for (int q = 0; q < 2; q++) {
            int m = m0 + tm * 4 + 2 * q;
            float4 r0, r1;
#pragma unroll
            for (int j = 0; j < 4; j++) {
                float2 v = *reinterpret_cast<float2*>(&acc[q][j]);
                (&r0.x)[j] = v.x + (&bv.x)[j];
                (&r1.x)[j] = v.y + (&bv.x)[j];
            }
            if (relu) {
#pragma unroll
                for (int j = 0; j < 4; j++) {
                    (&r0.x)[j] = fmaxf((&r0.x)[j], 0.f);
                    (&r1.x)[j] = fmaxf((&r1.x)[j], 0.f);
                }
            }
            *(float4*)(C + (size_t)m * N + n0 + tn * 4)       = r0;
            *(float4*)(C + (size_t)(m + 1) * N + n0 + tn * 4) = r1;
        }
    } else {
        float* P = part + (size_t)kz * M * N;
#pragma unroll
        for (int q = 0; q < 2; q++) {
            int m = m0 + tm * 4 + 2 * q;
            float4 r0, r1;
#pragma unroll
            for (int j = 0; j < 4; j++) {
                float2 v = *reinterpret_cast<float2*>(&acc[q][j]);
                (&r0.x)[j] = v.x;
                (&r1.x)[j] = v.y;
            }
            *(float4*)(P + (size_t)m * N + n0 + tn * 4)       = r0;
            *(float4*)(P + (size_t)(m + 1) * N + n0 + tn * 4) = r1;
        }
    }
}

// ---------------- split-K reduce: C = sum(partials) + bias (+relu) ----------------
__global__ void reduce_k(float* __restrict__ C, const float* __restrict__ part,
                         const float* __restrict__ bias, int MN, int N,
                         int nsplit, int relu)
{
    int i4 = (blockIdx.x * 256 + threadIdx.x) * 4;
    if (i4 >= MN) return;
    float4 s = *(const float4*)(part + i4);
    for (int z = 1; z < nsplit; z++) {
        float4 p = *(const float4*)(part + (size_t)z * MN + i4);
        s.x += p.x; s.y += p.y; s.z += p.z; s.w += p.w;
    }
    const float4 bv = *(const float4*)(bias + (i4 % N));
    s.x += bv.x; s.y += bv.y; s.z += bv.z; s.w += bv.w;
    if (relu) {
        s.x = fmaxf(s.x, 0.f); s.y = fmaxf(s.y, 0.f);
        s.z = fmaxf(s.z, 0.f); s.w = fmaxf(s.w, 0.f);
    }
    *(float4*)(C + i4) = s;
}

// ---------------- block reduction helper (256 threads) ----------------
__device__ __forceinline__ float blocksum256(float v)
{
    __shared__ float red[8];
    for (int o = 16; o; o >>= 1) v += __shfl_down_sync(0xffffffffu, v, o);
    if ((threadIdx.x & 31) == 0) red[threadIdx.x >> 5] = v;
    __syncthreads();
    if (threadIdx.x < 32) {
        float s = (threadIdx.x < 8) ? red[threadIdx.x] : 0.f;
        for (int o = 4; o; o >>= 1) s += __shfl_down_sync(0xffffffffu, s, o);
        if (threadIdx.x == 0) red[0] = s;
    }
    __syncthreads();
    float r = red[0];
    __syncthreads();
    return r;
}

// ---------------- self-attention (S<=16, per (b,h) block) ----------------
__global__ __launch_bounds__(256) void self_attn(
    const float* __restrict__ qkv, float* __restrict__ out, int S)
{
    const int b = blockIdx.x, h = blockIdx.y;
    __shared__ float q[T_][HD_ + 1], k[T_][HD_ + 1], v[T_][HD_ + 1];
    __shared__ float p[T_][T_ + 1];
    const int tid = threadIdx.x;

    for (int idx = tid; idx < S * HD_; idx += 256) {
        int s = idx >> 6, d = idx & 63;
        size_t base = ((size_t)(s * B_ + b)) * (3 * E_) + h * HD_ + d;
        q[s][d] = qkv[base];
        k[s][d] = qkv[base + E_];
        v[s][d] = qkv[base + 2 * E_];
    }
    __syncthreads();

    for (int idx = tid; idx < S * S; idx += 256) {
        int sq = idx / S, sk = idx - sq * S;
        float acc = 0.f;
#pragma unroll
        for (int d = 0; d < HD_; d++) acc = fmaf(q[sq][d], k[sk][d], acc);
        p[sq][sk] = acc * 0.125f;
    }
    __syncthreads();

    if (tid < S) {
        float mx = -3.4e38f;
        for (int sk = 0; sk < S; sk++) mx = fmaxf(mx, p[tid][sk]);
        float sum = 0.f;
        for (int sk = 0; sk < S; sk++) { float e = expf(p[tid][sk] - mx); p[tid][sk] = e; sum += e; }
        float inv = 1.f / sum;
        for (int sk = 0; sk < S; sk++) p[tid][sk] *= inv;
    }
    __syncthreads();

    for (int idx = tid; idx < S * HD_; idx += 256) {
        int s = idx >> 6, d = idx & 63;
        float acc = 0.f;
        for (int sk = 0; sk < S; sk++) acc = fmaf(p[s][sk], v[sk][d], acc);
        out[((size_t)(s * B_ + b)) * E_ + h * HD_ + d] = acc;
    }
}

// ---- fused: y=LN(xsrc+add); z=LN(y+c); x = LN(z + ff2(relu(ff1(z)))) ----
__global__ __launch_bounds__(256) void ln2ff(
    const float* __restrict__ xsrc, const float* __restrict__ add,
    const float* __restrict__ cc, float* __restrict__ xdst,
    const float* __restrict__ g0, const float* __restrict__ b0,
    const float* __restrict__ g1, const float* __restrict__ b1,
    const float* __restrict__ w1, const float* __restrict__ b1f,
    const float* __restrict__ w2, const float* __restrict__ b2f,
    const float* __restrict__ g2, const float* __restrict__ b2)
{
    const int row = blockIdx.x;
    const int bb  = row & (B_ - 1);
    const int tid = threadIdx.x;
    __shared__ float xs[E_];
    __shared__ float hs[F_];
    const float* xr = xsrc + (size_t)row * E_;
    const float* ar = add + (size_t)row * E_;
    const float* cr = cc + (size_t)bb * E_;

    float v0 = xr[tid] + ar[tid];
    float v1 = xr[tid + 256] + ar[tid + 256];

    float mean = blocksum256(v0 + v1) * (1.0f / (float)E_);
    float d0 = v0 - mean, d1 = v1 - mean;
    float var = blocksum256(d0 * d0 + d1 * d1) * (1.0f / (float)E_);
    float rs = rsqrtf(var + 1e-5f);
    float y0 = d0 * rs * g0[tid]       + b0[tid]       + cr[tid];
    float y1 = d1 * rs * g0[tid + 256] + b0[tid + 256] + cr[tid + 256];

    float mean2 = blocksum256(y0 + y1) * (1.0f / (float)E_);
    float e0 = y0 - mean2, e1 = y1 - mean2;
    float var2 = blocksum256(e0 * e0 + e1 * e1) * (1.0f / (float)E_);
    float rs2 = rsqrtf(var2 + 1e-5f);
    float z0 = e0 * rs2 * g1[tid]       + b1[tid];
    float z1 = e1 * rs2 * g1[tid + 256] + b1[tid + 256];

    xs[tid] = z0;
    xs[tid + 256] = z1;
    __syncthreads();

    // FF1: 32 units, 8 lanes each
    const int u = tid >> 3, l = tid & 7;
    const float4* w4  = reinterpret_cast<const float4*>(w1 + (size_t)u * E_);
    const float4* xs4 = reinterpret_cast<const float4*>(xs);
    float p = 0.f;
#pragma unroll
    for (int k4 = 0; k4 < 16; k4++) {
        float4 wv = w4[l + 8 * k4];
        float4 xv = xs4[l + 8 * k4];
        p += wv.x * xv.x + wv.y * xv.y + wv.z * xv.z + wv.w * xv.w;
    }
    for (int o = 4; o; o >>= 1) p += __shfl_down_sync(0xffffffffu, p, o, 8);
    if (l == 0) hs[u] = fmaxf(p + b1f[u], 0.f);
    __syncthreads();

    // FF2 + residual
    float a0 = b2f[tid]       + z0;
    float a1 = b2f[tid + 256] + z1;
    const float4* w20 = reinterpret_cast<const float4*>(w2 + (size_t)tid * F_);
    const float4* w21 = reinterpret_cast<const float4*>(w2 + (size_t)(tid + 256) * F_);
#pragma unroll
    for (int c4 = 0; c4 < 8; c4++) {
        float4 wa = w20[c4], wb = w21[c4];
        a0 = fmaf(hs[4*c4+0], wa.x, a0); a0 = fmaf(hs[4*c4+1], wa.y, a0);
        a0 = fmaf(hs[4*c4+2], wa.z, a0); a0 = fmaf(hs[4*c4+3], wa.w, a0);
        a1 = fmaf(hs[4*c4+0], wb.x, a1); a1 = fmaf(hs[4*c4+1], wb.y, a1);
        a1 = fmaf(hs[4*c4+2], wb.z, a1); a1 = fmaf(hs[4*c4+3], wb.w, a1);
    }

    float mean3 = blocksum256(a0 + a1) * (1.0f / (float)E_);
    float f0 = a0 - mean3, f1 = a1 - mean3;
    float var3 = blocksum256(f0 * f0 + f1 * f1) * (1.0f / (float)E_);
    float rs3 = rsqrtf(var3 + 1e-5f);
    float* xo = xdst + (size_t)row * E_;
    xo[tid]       = f0 * rs3 * g2[tid]       + b2[tid];
    xo[tid + 256] = f1 * rs3 * g2[tid + 256] + b2[tid + 256];
}

// ---- softmax + argmax + probs + token record + next-token append ----
__global__ __launch_bounds__(256) void softmax_append(
    const float* __restrict__ logits, float* __restrict__ probs,
    float* __restrict__ tokf,
    const float* __restrict__ emb, const float* __restrict__ pe,
    float* __restrict__ tb, int step, int do_append)
{
    const int b = blockIdx.x;
    const float* row = logits + (size_t)b * V_;
    const int tid = threadIdx.x;
    __shared__ float smx[256], ssm[256];
    __shared__ int   sidx[256];

    float mx = -3.4e38f, sm = 0.f; int mi = 0;
    for (int v = tid; v < V_; v += 256) {
        float val = row[v];
        if (val > mx) { sm = sm * expf(mx - val) + 1.f; mx = val; mi = v; }
        else          { sm += expf(val - mx); }
    }
    smx[tid] = mx; ssm[tid] = sm; sidx[tid] = mi;
    __syncthreads();
    for (int o = 128; o; o >>= 1) {
        if (tid < o) {
            float om = smx[tid + o], os = ssm[tid + o]; int oi = sidx[tid + o];
            float cm = smx[tid],     cs = ssm[tid];     int ci = sidx[tid];
            float nm = fmaxf(om, cm);
            ssm[tid] = cs * expf(cm - nm) + os * expf(om - nm);
            smx[tid] = nm;
            sidx[tid] = (om > cm || (om == cm && oi < ci)) ? oi : ci;
        }
        __syncthreads();
    }
    float m = smx[0];
    float inv = 1.0f / ssm[0];
    int amax = sidx[0];

    for (int v = tid; v < V_; v += 256)
        probs[(size_t)b * V_ + v] = expf(row[v] - m) * inv;

    if (tid == 0 && tokf)
        tokf[(size_t)b * T_ + step] = (float)amax;

    if (do_append) {
        size_t dst = ((size_t)(step + 1) * B_ + b) * E_;
        const float* er = emb + (size_t)amax * E_;
        const float* pr = pe + (size_t)step * E_;
        for (int e = tid; e < E_; e += 256)
            tb[dst + e] = er[e] + pr[e];
    }
}

// ---------------- misc small kernels ----------------
__global__ void pe_init(float* __restrict__ pe)
{
    int t = blockIdx.x;
    for (int i = threadIdx.x; i < E_ / 2; i += 256) {
        float div = expf((float)(2 * i) * (-logf(10000.0f) / (float)E_));
        float arg = (float)t * div;
        pe[t * E_ + 2 * i]     = sinf(arg);
        pe[t * E_ + 2 * i + 1] = cosf(arg);
    }
}

__global__ void init_x(const float* __restrict__ emb, float* __restrict__ tb)
{
    int b = blockIdx.x;
    for (int e = threadIdx.x; e < E_; e += 256)
        tb[(size_t)b * E_ + e] = emb[(size_t)SOS_ * E_ + e];
}

// ---------------- host-side GEMM dispatch ----------------
static float* s_sk = nullptr;

static inline void launch_gemm(const float* A, const float* W, const float* bias,
                               float* C, int M, int N, int K, int relu)
{
    int b128 = ((M % 128) == 0 && (N % 128) == 0) ? (M >> 7) * (N >> 7) : 0;
    if (b128 >= 120) {
        gemm128<<<dim3(N >> 7, M >> 7), 256>>>(A, W, bias, C, M, N, K, relu);
        return;
    }
    int bx = N >> 6, by = M >> 6;
    int b64 = bx * by;
    int nsplit = 1;
    if (b64 < 64) nsplit = 4;
    else if (b64 < 96) nsplit = 2;
    if (nsplit > 1 && (K % (16 * nsplit)) != 0) nsplit = 1;
    if (nsplit == 1) {
        gemm64<<<dim3(bx, by), 256>>>(A, W, bias, C, nullptr, M, N, K, relu, 1);
    } else {
        gemm64<<<dim3(bx, by, nsplit), 256>>>(A, W, bias, nullptr, s_sk,
                                              M, N, K, relu, nsplit);
        int MN = M * N;
        reduce_k<<<(MN / 4 + 255) / 256, 256>>>(C, s_sk, bias, MN, N, nsplit, relu);
    }
}

// ---------------- launcher ----------------
extern "C" void kernel_launch(void* const* d_in, const int* in_sizes, int n_in,
                              void* d_out, int out_size)
{
    const float* cur      = (const float*)d_in[0];
    const float* emb      = (const float*)d_in[1];
    const float* sa_in_w  = (const float*)d_in[2];
    const float* sa_in_b  = (const float*)d_in[3];
    const float* sa_out_w = (const float*)d_in[4];
    const float* sa_out_b = (const float*)d_in[5];
    const float* ca_in_w  = (const float*)d_in[6];
    const float* ca_in_b  = (const float*)d_in[7];
    const float* ca_out_w = (const float*)d_in[8];
    const float* ca_out_b = (const float*)d_in[9];
    const float* ff1_w    = (const float*)d_in[10];
    const float* ff1_b    = (const float*)d_in[11];
    const float* ff2_w    = (const float*)d_in[12];
    const float* ff2_b    = (const float*)d_in[13];
    const float* ln_g     = (const float*)d_in[14];
    const float* ln_b     = (const float*)d_in[15];
    const float* out_w    = (const float*)d_in[16];
    const float* out_b    = (const float*)d_in[17];

    float *tb, *x, *qkv0, *qkv, *attn, *tmp, *cb, *hv, *pe, *logits;
    cudaGetSymbolAddress((void**)&tb,     g_tb);
    cudaGetSymbolAddress((void**)&x,      g_x);
    cudaGetSymbolAddress((void**)&qkv0,   g_qkv0);
    cudaGetSymbolAddress((void**)&qkv,    g_qkv);
    cudaGetSymbolAddress((void**)&attn,   g_attn);
    cudaGetSymbolAddress((void**)&tmp,    g_tmp);
    cudaGetSymbolAddress((void**)&cb,     g_c);
    cudaGetSymbolAddress((void**)&hv,     g_hv);
    cudaGetSymbolAddress((void**)&pe,     g_pe);
    cudaGetSymbolAddress((void**)&logits, g_logits);
    cudaGetSymbolAddress((void**)&s_sk,   g_sk);

    float* outp = (float*)d_out;
    long long tok_elems = (long long)out_size - (long long)T_ * B_ * V_;
    float* tokf = (tok_elems > 0) ? outp : nullptr;
    float* probs_base = (tok_elems > 0) ? (outp + tok_elems) : outp;

    pe_init<<<T_, 256>>>(pe);
    init_x<<<B_, 256>>>(emb, tb);

    // Cross-attention collapses (kv seq len 1 => softmax == 1):
    // c[l][b] = ca_out_w[l] @ (ca_wv[l] @ cur_b + bv) + ca_out_b[l]
    for (int l = 0; l < L_; l++) {
        launch_gemm(cur, ca_in_w + ((size_t)l * 3 * E_ + 2 * E_) * E_,
                    ca_in_b + (size_t)l * 3 * E_ + 2 * E_, hv, B_, E_, E_, 0);
        launch_gemm(hv, ca_out_w + (size_t)l * E_ * E_, ca_out_b + (size_t)l * E_,
                    cb + (size_t)l * B_ * E_, B_, E_, E_, 0);
    }

    for (int i = 0; i < T_; i++) {
        const int S = i + 1;
        const int M = S * B_;

        for (int l = 0; l < L_; l++) {
            const float* qkv_src;
            if (l == 0) {
                // layer-0 input rows are immutable across steps: only new row
                launch_gemm(tb + (size_t)i * B_ * E_,
                            sa_in_w, sa_in_b,
                            qkv0 + (size_t)i * B_ * 3 * E_,
                            B_, 3 * E_, E_, 0);
                qkv_src = qkv0;
            } else {
                launch_gemm(x, sa_in_w + (size_t)l * 3 * E_ * E_,
                            sa_in_b + (size_t)l * 3 * E_,
                            qkv, M, 3 * E_, E_, 0);
                qkv_src = qkv;
            }
            self_attn<<<dim3(B_, H_), 256>>>(qkv_src, attn, S);
            launch_gemm(attn, sa_out_w + (size_t)l * E_ * E_,
                        sa_out_b + (size_t)l * E_, tmp, M, E_, E_, 0);
            // fused: LN(residual) + cross-const + LN + FF + LN
            // layer 0 reads tb (x not yet initialized this step)
            ln2ff<<<M, 256>>>((l == 0) ? tb : x, tmp,
                              cb + (size_t)l * B_ * E_, x,
                              ln_g + (size_t)(l * 3 + 0) * E_,
                              ln_b + (size_t)(l * 3 + 0) * E_,
                              ln_g + (size_t)(l * 3 + 1) * E_,
                              ln_b + (size_t)(l * 3 + 1) * E_,
                              ff1_w + (size_t)l * F_ * E_, ff1_b + (size_t)l * F_,
                              ff2_w + (size_t)l * E_ * F_, ff2_b + (size_t)l * E_,
                              ln_g + (size_t)(l * 3 + 2) * E_,
                              ln_b + (size_t)(l * 3 + 2) * E_);
        }

        // logits for last position, then fused softmax/argmax/probs/append
        launch_gemm(x + (size_t)(S - 1) * B_ * E_, out_w, out_b, logits,
                    B_, V_, E_, 0);
        softmax_append<<<B_, 256>>>(logits, probs_base + (size_t)i * B_ * V_,
                                    tokf, emb, pe, tb, i, (i + 1 < T_) ? 1 : 0);
    }
}